// round 13
// baseline (speedup 1.0000x reference)
#include <cuda_runtime.h>
#include <cuda_fp16.h>
#include <math_constants.h>
#include <cstdint>

// Problem constants
#define B_SZ    2
#define N_SEQ   2048
#define DMODEL  2048
#define HQ      32
#define HKV     8
#define DHEAD   64
#define QKV_DIM 3072
#define TOKENS  4096
#define NH_ALL  48            // q(32) + k(8) + v(8)

// Scratch (allocation-free device globals)
__device__ float  g_qkv[(size_t)TOKENS * QKV_DIM];    // fp32 QKV (gemm out)
__device__ __half g_qkvh[(size_t)TOKENS * QKV_DIM];   // fp16 normed/roped
__device__ __half g_xh[(size_t)TOKENS * DMODEL];      // fp16 x
__device__ __half g_wqh[(size_t)QKV_DIM * DMODEL];    // fp16 qkv_w
__device__ __half g_woh[(size_t)DMODEL * DMODEL];     // fp16 out_w
__device__ __half g_yh[(size_t)TOKENS * DMODEL];      // fp16 attn out

__device__ __forceinline__ uint32_t packh2(float a, float b) {
    __half2 h = __floats2half2_rn(a, b);
    return *(uint32_t*)&h;
}

__device__ __forceinline__ void mma_f16(float c[4], const uint32_t a[4],
                                        const uint32_t b[2]) {
    asm volatile(
        "mma.sync.aligned.m16n8k16.row.col.f32.f16.f16.f32 "
        "{%0,%1,%2,%3}, {%4,%5,%6,%7}, {%8,%9}, {%0,%1,%2,%3};\n"
        : "+f"(c[0]), "+f"(c[1]), "+f"(c[2]), "+f"(c[3])
        : "r"(a[0]), "r"(a[1]), "r"(a[2]), "r"(a[3]), "r"(b[0]), "r"(b[1]));
}

__device__ __forceinline__ uint32_t smem_u32(const void* p) {
    uint32_t a;
    asm("{ .reg .u64 t; cvta.to.shared.u64 t, %1; cvt.u32.u64 %0, t; }"
        : "=r"(a) : "l"(p));
    return a;
}

__device__ __forceinline__ void cp16(uint32_t saddr, const void* gptr) {
    asm volatile("cp.async.cg.shared.global [%0], [%1], 16;"
                 :: "r"(saddr), "l"(gptr));
}

// ---------------------------------------------------------------------------
// fp32 -> fp16 grid-stride converter (n % 4 == 0)
// ---------------------------------------------------------------------------
__global__ void f32h(const float* __restrict__ in, __half* __restrict__ out,
                     int n4) {
    int i = blockIdx.x * blockDim.x + threadIdx.x;
    if (i >= n4) return;
    float4 v = *(const float4*)(in + (size_t)i * 4);
    uint2 p;
    p.x = packh2(v.x, v.y);
    p.y = packh2(v.z, v.w);
    *(uint2*)(out + (size_t)i * 4) = p;
}

// ---------------------------------------------------------------------------
// FP16-in GEMM via cp.async fragment-direct staging.
// C[M,N](fp32) = A[M,K] * B[N,K]^T, A/B fp16 K-major.
// 128x128 CTA tile, BK=32, 8 warps (2x4), warp tile 64x32.
// Fragment layout [tile][ik][reg][g][j]: a thread's 16B global chunk is 16B
// contiguous in smem -> single cp.async per chunk. MMA loads are coalesced
// LDS.32 (addr = base + lane). 3-stage pipeline, 1 barrier/K-step.
// ---------------------------------------------------------------------------
__global__ __launch_bounds__(256, 2) void gemm_h16(const __half* __restrict__ A,
                                                   const __half* __restrict__ Bm,
                                                   float* __restrict__ C,
                                                   int M, int N, int K) {
    __shared__ uint32_t Afr[3][2048];   // 8KB per stage
    __shared__ uint32_t Bfr[3][2048];   // 8KB per stage

    const int tid = threadIdx.x;
    const int lane = tid & 31, warp = tid >> 5;
    const int wm = warp >> 2, wn = warp & 3;   // 2 x 4
    const size_t bm = (size_t)blockIdx.y * 128, bn = (size_t)blockIdx.x * 128;

    const __half* Ab = A + bm * K;
    const __half* Bb = Bm + bn * K;

    // Per-thread staging coords: 2 chunks of A, 2 of B.
    uint32_t awB[2], bwB[2];            // dst byte offsets within a stage
    const __half* asrc[2];
    const __half* bsrc[2];
#pragma unroll
    for (int s = 0; s < 2; s++) {
        int idx = tid + s * 256;
        int row = idx >> 2, c = idx & 3;
        int im = row >> 4, ishi = (row >> 3) & 1, g = row & 7;
        int ik = c >> 1, hk = c & 1, r = ishi + 2 * hk;
        awB[s] = (uint32_t)((((im * 2 + ik) * 4 + r) * 8 + g) * 4) * 4u;
        int in = row >> 3;
        bwB[s] = (uint32_t)((((in * 2 + ik) * 2 + hk) * 8 + g) * 4) * 4u;
        asrc[s] = Ab + (size_t)row * K + c * 8;
        bsrc[s] = Bb + (size_t)row * K + c * 8;
    }
    const uint32_t sA = smem_u32(Afr);
    const uint32_t sB = smem_u32(Bfr);

    float acc[4][4][4];
#pragma unroll
    for (int im = 0; im < 4; im++)
#pragma unroll
        for (int in = 0; in < 4; in++)
#pragma unroll
            for (int j = 0; j < 4; j++) acc[im][in][j] = 0.f;

#define STAGE_CP(slot, k0)                                                     \
    {                                                                          \
        uint32_t so = (uint32_t)(slot) * 8192u;                                \
        _Pragma("unroll")                                                      \
        for (int s = 0; s < 2; s++) {                                          \
            cp16(sA + so + awB[s], asrc[s] + (k0));                            \
            cp16(sB + so + bwB[s], bsrc[s] + (k0));                            \
        }                                                                      \
        asm volatile("cp.async.commit_group;");                                \
    }

    const int NIT = K / 32;
    STAGE_CP(0, 0);
    STAGE_CP(1, 32);

    for (int it = 0; it < NIT; it++) {
        asm volatile("cp.async.wait_group 1;");
        __syncthreads();

        if (it + 2 < NIT) {
            int slot = (it + 2) % 3;
            STAGE_CP(slot, (it + 2) * 32);
        } else {
            asm volatile("cp.async.commit_group;");
        }

        const uint32_t* Ac = Afr[it % 3];
        const uint32_t* Bc = Bfr[it % 3];
#pragma unroll
        for (int ik = 0; ik < 2; ik++) {
            uint32_t af[4][4];
            uint32_t bf[4][2];
#pragma unroll
            for (int im = 0; im < 4; im++)
#pragma unroll
                for (int r = 0; r < 4; r++)
                    af[im][r] = Ac[(((wm * 4 + im) * 2 + ik) * 4 + r) * 32 + lane];
#pragma unroll
            for (int in = 0; in < 4; in++)
#pragma unroll
                for (int hk = 0; hk < 2; hk++)
                    bf[in][hk] = Bc[(((wn * 4 + in) * 2 + ik) * 2 + hk) * 32 + lane];
#pragma unroll
            for (int im = 0; im < 4; im++)
#pragma unroll
                for (int in = 0; in < 4; in++)
                    mma_f16(acc[im][in], af[im], bf[in]);
        }
    }

#pragma unroll
    for (int im = 0; im < 4; im++) {
#pragma unroll
        for (int in = 0; in < 4; in++) {
            size_t r0 = bm + wm * 64 + im * 16 + (lane >> 2);
            size_t c0 = bn + wn * 32 + in * 8 + (lane & 3) * 2;
            *(float2*)&C[r0 * N + c0] = make_float2(acc[im][in][0], acc[im][in][1]);
            *(float2*)&C[(r0 + 8) * N + c0] = make_float2(acc[im][in][2], acc[im][in][3]);
        }
    }
#undef STAGE_CP
}

// ---------------------------------------------------------------------------
// Fused per-head RMSNorm + RoPE + fp16 pack, vectorized (R12 version).
// ---------------------------------------------------------------------------
__global__ void norm_rope_h(const int* __restrict__ pos,
                            const float* __restrict__ qw,
                            const float* __restrict__ kw) {
    int gw = (blockIdx.x * blockDim.x + threadIdx.x) >> 5;
    int lane = threadIdx.x & 31;
    int grp = lane >> 3, li = lane & 7;
    int idx = gw * 4 + grp;
    if (idx >= TOKENS * NH_ALL) return;
    int token = idx / NH_ALL;
    int h = idx - token * NH_ALL;

    const float* ptr = g_qkv + (size_t)token * QKV_DIM + h * DHEAD;
    __half* outp = g_qkvh + (size_t)token * QKV_DIM + h * DHEAD;
    float4 x1 = *(const float4*)(ptr + li * 4);
    float4 x2 = *(const float4*)(ptr + 32 + li * 4);

    if (h >= HQ + HKV) {   // v: plain convert
        uint2 p1, p2;
        p1.x = packh2(x1.x, x1.y); p1.y = packh2(x1.z, x1.w);
        p2.x = packh2(x2.x, x2.y); p2.y = packh2(x2.z, x2.w);
        *(uint2*)(outp + li * 4) = p1;
        *(uint2*)(outp + 32 + li * 4) = p2;
        return;
    }

    int p = pos[token & (N_SEQ - 1)];
    float ss = x1.x * x1.x + x1.y * x1.y + x1.z * x1.z + x1.w * x1.w
             + x2.x * x2.x + x2.y * x2.y + x2.z * x2.z + x2.w * x2.w;
    ss += __shfl_xor_sync(0xffffffffu, ss, 1);
    ss += __shfl_xor_sync(0xffffffffu, ss, 2);
    ss += __shfl_xor_sync(0xffffffffu, ss, 4);
    float r = rsqrtf(ss * (1.0f / 64.0f) + 1e-6f);

    const float* wv = (h < HQ) ? qw : kw;
    float4 w1 = *(const float4*)(wv + li * 4);
    float4 w2 = *(const float4*)(wv + 32 + li * 4);
    float sc = (h < HQ) ? 0.125f : 1.0f;

    float a1[4] = {x1.x * r * w1.x, x1.y * r * w1.y, x1.z * r * w1.z, x1.w * r * w1.w};
    float a2[4] = {x2.x * r * w2.x, x2.y * r * w2.y, x2.z * r * w2.z, x2.w * r * w2.w};

    float y1[4], y2[4];
#pragma unroll
    for (int j = 0; j < 4; j++) {
        int d = li * 4 + j;
        float inv = expf(-(float)(2 * d) * (9.210340371976184f / 64.0f));
        float sv, cv;
        sincosf((float)p * inv, &sv, &cv);
        y1[j] = (a1[j] * cv - a2[j] * sv) * sc;
        y2[j] = (a1[j] * sv + a2[j] * cv) * sc;
    }
    uint2 p1, p2;
    p1.x = packh2(y1[0], y1[1]); p1.y = packh2(y1[2], y1[3]);
    p2.x = packh2(y2[0], y2[1]); p2.y = packh2(y2[2], y2[3]);
    *(uint2*)(outp + li * 4) = p1;
    *(uint2*)(outp + 32 + li * 4) = p2;
}

// ---------------------------------------------------------------------------
// FP16 tensor-core causal GQA flash attention (unchanged from R11/R12 best).
// ---------------------------------------------------------------------------
#define ATTN_SMEM_WORDS (4096 + 2048 + 2048 + 4096)
#define ATTN_SMEM_BYTES (ATTN_SMEM_WORDS * 4)

__global__ __launch_bounds__(256) void attn_mma() {
    extern __shared__ uint32_t smu[];
    uint32_t* Qfr = smu;             // 4096
    uint32_t* Kfr = smu + 4096;      // 2048
    uint32_t* Vfr = smu + 6144;      // 2048
    uint32_t* Pfr = smu + 8192;      // 4096: per-warp 512

    int qb = (gridDim.x - 1) - blockIdx.x;
    int h = blockIdx.y, b = blockIdx.z;
    int hk4 = h >> 2;
    int tid = threadIdx.x, lane = tid & 31, w = tid >> 5;
    int g = lane >> 2, t = lane & 3;
    size_t base = (size_t)b * N_SEQ;
    int q0 = qb * 128;

#pragma unroll
    for (int s = 0; s < 4; s++) {
        int idx = tid + s * 256;
        int row = idx >> 3, c = idx & 7;
        uint4 qv = *(const uint4*)&g_qkvh[(base + q0 + row) * QKV_DIM + h * DHEAD + c * 8];
        int wq = row >> 4, ishi = (row >> 3) & 1, gq = row & 7;
        int hh = c & 1, ik = c >> 1;
        const uint32_t* pq = (const uint32_t*)&qv;
#pragma unroll
        for (int j = 0; j < 4; j++) {
            int slot = (gq * 4 + j) ^ ((ik & 3) * 4);
            Qfr[((wq * 4 + ik) * 32 + slot) * 4 + ishi + 2 * hh] = pq[j];
        }
    }

    uint4 rk[2], rv[2];
    const int nb = 2 * qb + 2;

#define LOADKV(kb_)                                                            \
    {                                                                          \
        int k0_ = (kb_) * 64;                                                  \
        _Pragma("unroll")                                                      \
        for (int s = 0; s < 2; s++) {                                          \
            int idx = tid + s * 256;                                           \
            int key = idx >> 3, c = idx & 7;                                   \
            size_t toff = (base + k0_ + key) * QKV_DIM;                        \
            rk[s] = *(const uint4*)&g_qkvh[toff + (HQ + hk4) * DHEAD + c * 8]; \
            rv[s] = *(const uint4*)&g_qkvh[toff + (HQ + HKV + hk4) * DHEAD + c * 8]; \
        }                                                                      \
    }

#define STAGEKV()                                                              \
    {                                                                          \
        __half* vh = (__half*)Vfr;                                             \
        _Pragma("unroll")                                                      \
        for (int s = 0; s < 2; s++) {                                          \
            int idx = tid + s * 256;                                           \
            int key = idx >> 3, c = idx & 7;                                   \
            int in = key >> 3, gb = key & 7;                                   \
            int hh = c & 1, ik = c >> 1;                                       \
            const uint32_t* pk = (const uint32_t*)&rk[s];                      \
            _Pragma("unroll")                                                  \
            for (int j = 0; j < 4; j++) {                                      \
                int slK = (gb * 4 + j) ^ ((ik & 3) * 4);                       \
                Kfr[((in * 4 + ik) * 32 + slK) * 2 + hh] = pk[j];              \
            }                                                                  \
            int tv = (key >> 1) & 3, hv = (key >> 3) & 1, ikv = key >> 4;      \
            int keylo = key & 1;                                               \
            const __half* ph = (const __half*)&rv[s];                          \
            _Pragma("unroll")                                                  \
            for (int e = 0; e < 8; e++) {                                      \
                int d = c * 8 + e;                                             \
                int dt = d >> 3, gv = d & 7;                                   \
                int slV = (gv * 4 + tv) ^ ((dt & 3) * 4);                      \
                int hidx = ((((ikv * 8 + dt) * 32 + slV) * 2 + hv) << 1) | keylo; \
                vh[hidx] = ph[e];                                              \
            }                                                                  \
        }                                                                      \
    }

    float m0 = -CUDART_INF_F, m1 = -CUDART_INF_F, l0 = 0.f, l1 = 0.f;
    float o[8][4];
#pragma unroll
    for (int dt = 0; dt < 8; dt++)
#pragma unroll
        for (int j = 0; j < 4; j++) o[dt][j] = 0.f;

    uint32_t* Pw = Pfr + w * 512;
    const int row0 = q0 + w * 16 + g;

    LOADKV(0);

    for (int kb = 0; kb < nb; kb++) {
        if (kb > 0) __syncthreads();
        STAGEKV();
        __syncthreads();
        if (kb + 1 < nb) LOADKV(kb + 1);

        float sacc[8][4];
#pragma unroll
        for (int n = 0; n < 8; n++)
#pragma unroll
            for (int j = 0; j < 4; j++) sacc[n][j] = 0.f;

#pragma unroll
        for (int ik = 0; ik < 4; ik++) {
            uint4 aq = *(const uint4*)&Qfr[((w * 4 + ik) * 32 + (lane ^ ((ik & 3) * 4))) * 4];
            const uint32_t a4[4] = {aq.x, aq.y, aq.z, aq.w};
#pragma unroll
            for (int n = 0; n < 8; n++) {
                uint2 bk = *(const uint2*)&Kfr[((n * 4 + ik) * 32 + (lane ^ ((ik & 3) * 4))) * 2];
                const uint32_t b2[2] = {bk.x, bk.y};
                mma_f16(sacc[n], a4, b2);
            }
        }

        if (kb >= 2 * qb) {
            int k0 = kb * 64;
#pragma unroll
            for (int n = 0; n < 8; n++) {
                int cb = k0 + n * 8 + 2 * t;
                if (cb > row0)     sacc[n][0] = -1e30f;
                if (cb + 1 > row0) sacc[n][1] = -1e30f;
                if (cb > row0 + 8)     sacc[n][2] = -1e30f;
                if (cb + 1 > row0 + 8) sacc[n][3] = -1e30f;
            }
        }

        float mx0 = -1e30f, mx1 = -1e30f;
#pragma unroll
        for (int n = 0; n < 8; n++) {
            mx0 = fmaxf(mx0, fmaxf(sacc[n][0], sacc[n][1]));
            mx1 = fmaxf(mx1, fmaxf(sacc[n][2], sacc[n][3]));
        }
        mx0 = fmaxf(mx0, __shfl_xor_sync(0xffffffffu, mx0, 1));
        mx0 = fmaxf(mx0, __shfl_xor_sync(0xffffffffu, mx0, 2));
        mx1 = fmaxf(mx1, __shfl_xor_sync(0xffffffffu, mx1, 1));
        mx1 = fmaxf(mx1, __shfl_xor_sync(0xffffffffu, mx1, 2));

        float mn0 = fmaxf(m0, mx0), mn1 = fmaxf(m1, mx1);
        float c0 = __expf(m0 - mn0), c1 = __expf(m1 - mn1);
        float s0 = 0.f, s1 = 0.f;
#pragma unroll
        for (int n = 0; n < 8; n++) {
            sacc[n][0] = __expf(sacc[n][0] - mn0);
            sacc[n][1] = __expf(sacc[n][1] - mn0);
            sacc[n][2] = __expf(sacc[n][2] - mn1);
            sacc[n][3] = __expf(sacc[n][3] - mn1);
            s0 += sacc[n][0] + sacc[n][1];
            s1 += sacc[n][2] + sacc[n][3];
        }
        s0 += __shfl_xor_sync(0xffffffffu, s0, 1);
        s0 += __shfl_xor_sync(0xffffffffu, s0, 2);
        s1 += __shfl_xor_sync(0xffffffffu, s1, 1);
        s1 += __shfl_xor_sync(0xffffffffu, s1, 2);
        l0 = l0 * c0 + s0; l1 = l1 * c1 + s1;
        m0 = mn0; m1 = mn1;
#pragma unroll
        for (int dt = 0; dt < 8; dt++) {
            o[dt][0] *= c0; o[dt][1] *= c0;
            o[dt][2] *= c1; o[dt][3] *= c1;
        }

#pragma unroll
        for (int n = 0; n < 8; n++) {
            int ikp = n >> 1, hkp = n & 1;
            Pw[(ikp * 32 + g * 4 + t) * 4 + 0 + 2 * hkp] = packh2(sacc[n][0], sacc[n][1]);
            Pw[(ikp * 32 + g * 4 + t) * 4 + 1 + 2 * hkp] = packh2(sacc[n][2], sacc[n][3]);
        }
        __syncwarp();

#pragma unroll
        for (int ik = 0; ik < 4; ik++) {
            uint4 ap = *(const uint4*)&Pw[(ik * 32 + lane) * 4];
            const uint32_t a4[4] = {ap.x, ap.y, ap.z, ap.w};
#pragma unroll
            for (int dt = 0; dt < 8; dt++) {
                uint2 bv = *(const uint2*)&Vfr[((ik * 8 + dt) * 32 + (lane ^ ((dt & 3) * 4))) * 2];
                const uint32_t b2[2] = {bv.x, bv.y};
                mma_f16(o[dt], a4, b2);
            }
        }
    }

    float i0 = 1.f / l0, i1 = 1.f / l1;
#pragma unroll
    for (int dt = 0; dt < 8; dt++) {
        int col = h * DHEAD + dt * 8 + 2 * t;
        *(uint32_t*)&g_yh[(base + row0) * DMODEL + col] = packh2(o[dt][0] * i0, o[dt][1] * i0);
        *(uint32_t*)&g_yh[(base + row0 + 8) * DMODEL + col] = packh2(o[dt][2] * i1, o[dt][3] * i1);
    }
#undef LOADKV
#undef STAGEKV
}

// ---------------------------------------------------------------------------
// Launch
// ---------------------------------------------------------------------------
extern "C" void kernel_launch(void* const* d_in, const int* in_sizes, int n_in,
                              void* d_out, int out_size) {
    const float* x     = (const float*)d_in[0];
    const int*   pos   = (const int*)d_in[2];
    const float* qkv_w = (const float*)d_in[3];
    const float* out_w = (const float*)d_in[4];
    const float* qnw   = (const float*)d_in[5];
    const float* knw   = (const float*)d_in[6];
    float* out = (float*)d_out;

    float *qkv_buf;
    __half *xh, *wqh, *woh, *yh;
    cudaGetSymbolAddress((void**)&qkv_buf, g_qkv);
    cudaGetSymbolAddress((void**)&xh, g_xh);
    cudaGetSymbolAddress((void**)&wqh, g_wqh);
    cudaGetSymbolAddress((void**)&woh, g_woh);
    cudaGetSymbolAddress((void**)&yh, g_yh);

    // 0) one-time fp16 conversions
    {
        int n4;
        n4 = TOKENS * DMODEL / 4;
        f32h<<<(n4 + 255) / 256, 256>>>(x, xh, n4);
        n4 = QKV_DIM * DMODEL / 4;
        f32h<<<(n4 + 255) / 256, 256>>>(qkv_w, wqh, n4);
        n4 = DMODEL * DMODEL / 4;
        f32h<<<(n4 + 255) / 256, 256>>>(out_w, woh, n4);
    }
    // 1) QKV projection (cp.async pipeline)
    gemm_h16<<<dim3(QKV_DIM / 128, TOKENS / 128), 256>>>(xh, wqh, qkv_buf,
                                                         TOKENS, QKV_DIM, DMODEL);
    // 2) RMSNorm + RoPE + fp16 pack
    {
        int nidx = TOKENS * NH_ALL;
        int warps = (nidx + 3) / 4;
        int threads = warps * 32;
        norm_rope_h<<<(threads + 255) / 256, 256>>>(pos, qnw, knw);
    }
    // 3) Attention (fp16 in, fp16 out)
    cudaFuncSetAttribute(attn_mma, cudaFuncAttributeMaxDynamicSharedMemorySize,
                         ATTN_SMEM_BYTES);
    attn_mma<<<dim3(N_SEQ / 128, HQ, B_SZ), 256, ATTN_SMEM_BYTES>>>();
    // 4) Output projection
    gemm_h16<<<dim3(DMODEL / 128, TOKENS / 128), 256>>>(yh, woh, out,
                                                        TOKENS, DMODEL, DMODEL);
}

// round 15
// speedup vs baseline: 1.0004x; 1.0004x over previous
#include <cuda_runtime.h>
#include <cuda_fp16.h>
#include <math_constants.h>
#include <cstdint>

// Problem constants
#define B_SZ    2
#define N_SEQ   2048
#define DMODEL  2048
#define HQ      32
#define HKV     8
#define DHEAD   64
#define QKV_DIM 3072
#define TOKENS  4096
#define NH_ALL  48            // q(32) + k(8) + v(8)

// Scratch (allocation-free device globals)
__device__ float  g_qkv[(size_t)TOKENS * QKV_DIM];    // fp32 QKV (gemm out)
__device__ __half g_qkvh[(size_t)TOKENS * QKV_DIM];   // fp16 normed/roped
__device__ __half g_xh[(size_t)TOKENS * DMODEL];      // fp16 x
__device__ __half g_wqh[(size_t)QKV_DIM * DMODEL];    // fp16 qkv_w
__device__ __half g_woh[(size_t)DMODEL * DMODEL];     // fp16 out_w
__device__ __half g_yh[(size_t)TOKENS * DMODEL];      // fp16 attn out

__device__ __forceinline__ uint32_t packh2(float a, float b) {
    __half2 h = __floats2half2_rn(a, b);
    return *(uint32_t*)&h;
}

__device__ __forceinline__ void mma_f16(float c[4], const uint32_t a[4],
                                        const uint32_t b[2]) {
    asm volatile(
        "mma.sync.aligned.m16n8k16.row.col.f32.f16.f16.f32 "
        "{%0,%1,%2,%3}, {%4,%5,%6,%7}, {%8,%9}, {%0,%1,%2,%3};\n"
        : "+f"(c[0]), "+f"(c[1]), "+f"(c[2]), "+f"(c[3])
        : "r"(a[0]), "r"(a[1]), "r"(a[2]), "r"(a[3]), "r"(b[0]), "r"(b[1]));
}

__device__ __forceinline__ uint32_t smem_u32(const void* p) {
    uint32_t a;
    asm("{ .reg .u64 t; cvta.to.shared.u64 t, %1; cvt.u32.u64 %0, t; }"
        : "=r"(a) : "l"(p));
    return a;
}

__device__ __forceinline__ void cp16(uint32_t saddr, const void* gptr) {
    asm volatile("cp.async.cg.shared.global [%0], [%1], 16;"
                 :: "r"(saddr), "l"(gptr));
}

// ---------------------------------------------------------------------------
// fp32 -> fp16 grid-stride converter (n % 4 == 0)
// ---------------------------------------------------------------------------
__global__ void f32h(const float* __restrict__ in, __half* __restrict__ out,
                     int n4) {
    int i = blockIdx.x * blockDim.x + threadIdx.x;
    if (i >= n4) return;
    float4 v = *(const float4*)(in + (size_t)i * 4);
    uint2 p;
    p.x = packh2(v.x, v.y);
    p.y = packh2(v.z, v.w);
    *(uint2*)(out + (size_t)i * 4) = p;
}

// ---------------------------------------------------------------------------
// FP16-in GEMM via cp.async fragment-direct staging, 4-stage pipeline.
// C[M,N](fp32) = A[M,K] * B[N,K]^T, A/B fp16 K-major.
// 128x128 CTA tile, BK=32, 8 warps (2x4), warp tile 64x32.
// wait_group 2: prefetch distance = 3 K-steps (~600cy cover).
// 64KB DYNAMIC smem (static cap is 48KB). Stage layout:
//   stage s (16KB): A frags at +s*16384, B frags at +s*16384+8192.
// ---------------------------------------------------------------------------
#define GEMM_SMEM_BYTES (4 * 16384)

__global__ __launch_bounds__(256, 2) void gemm_h16(const __half* __restrict__ A,
                                                   const __half* __restrict__ Bm,
                                                   float* __restrict__ C,
                                                   int M, int N, int K) {
    extern __shared__ uint32_t gsm[];

    const int tid = threadIdx.x;
    const int lane = tid & 31, warp = tid >> 5;
    const int wm = warp >> 2, wn = warp & 3;   // 2 x 4
    const size_t bm = (size_t)blockIdx.y * 128, bn = (size_t)blockIdx.x * 128;

    const __half* Ab = A + bm * K;
    const __half* Bb = Bm + bn * K;

    // Per-thread staging coords: 2 chunks of A, 2 of B.
    uint32_t awB[2], bwB[2];            // dst byte offsets within a stage
    const __half* asrc[2];
    const __half* bsrc[2];
#pragma unroll
    for (int s = 0; s < 2; s++) {
        int idx = tid + s * 256;
        int row = idx >> 2, c = idx & 3;
        int im = row >> 4, ishi = (row >> 3) & 1, g = row & 7;
        int ik = c >> 1, hk = c & 1, r = ishi + 2 * hk;
        awB[s] = (uint32_t)((((im * 2 + ik) * 4 + r) * 8 + g) * 4) * 4u;
        int in = row >> 3;
        bwB[s] = 8192u + (uint32_t)((((in * 2 + ik) * 2 + hk) * 8 + g) * 4) * 4u;
        asrc[s] = Ab + (size_t)row * K + c * 8;
        bsrc[s] = Bb + (size_t)row * K + c * 8;
    }
    const uint32_t sBase = smem_u32(gsm);

    float acc[4][4][4];
#pragma unroll
    for (int im = 0; im < 4; im++)
#pragma unroll
        for (int in = 0; in < 4; in++)
#pragma unroll
            for (int j = 0; j < 4; j++) acc[im][in][j] = 0.f;

#define STAGE_CP(slot, k0)                                                     \
    {                                                                          \
        uint32_t so = sBase + (uint32_t)(slot) * 16384u;                       \
        _Pragma("unroll")                                                      \
        for (int s = 0; s < 2; s++) {                                          \
            cp16(so + awB[s], asrc[s] + (k0));                                 \
            cp16(so + bwB[s], bsrc[s] + (k0));                                 \
        }                                                                      \
        asm volatile("cp.async.commit_group;");                                \
    }

    const int NIT = K / 32;
    STAGE_CP(0, 0);
    STAGE_CP(1, 32);
    STAGE_CP(2, 64);

    for (int it = 0; it < NIT; it++) {
        asm volatile("cp.async.wait_group 2;");
        __syncthreads();

        if (it + 3 < NIT) {
            int slot = (it + 3) & 3;
            STAGE_CP(slot, (it + 3) * 32);
        } else {
            asm volatile("cp.async.commit_group;");
        }

        const uint32_t* Ac = gsm + (it & 3) * 4096;        // words
        const uint32_t* Bc = Ac + 2048;
#pragma unroll
        for (int ik = 0; ik < 2; ik++) {
            uint32_t af[4][4];
            uint32_t bf[4][2];
#pragma unroll
            for (int im = 0; im < 4; im++)
#pragma unroll
                for (int r = 0; r < 4; r++)
                    af[im][r] = Ac[(((wm * 4 + im) * 2 + ik) * 4 + r) * 32 + lane];
#pragma unroll
            for (int in = 0; in < 4; in++)
#pragma unroll
                for (int hk = 0; hk < 2; hk++)
                    bf[in][hk] = Bc[(((wn * 4 + in) * 2 + ik) * 2 + hk) * 32 + lane];
#pragma unroll
            for (int im = 0; im < 4; im++)
#pragma unroll
                for (int in = 0; in < 4; in++)
                    mma_f16(acc[im][in], af[im], bf[in]);
        }
    }

#pragma unroll
    for (int im = 0; im < 4; im++) {
#pragma unroll
        for (int in = 0; in < 4; in++) {
            size_t r0 = bm + wm * 64 + im * 16 + (lane >> 2);
            size_t c0 = bn + wn * 32 + in * 8 + (lane & 3) * 2;
            *(float2*)&C[r0 * N + c0] = make_float2(acc[im][in][0], acc[im][in][1]);
            *(float2*)&C[(r0 + 8) * N + c0] = make_float2(acc[im][in][2], acc[im][in][3]);
        }
    }
#undef STAGE_CP
}

// ---------------------------------------------------------------------------
// Fused per-head RMSNorm + RoPE + fp16 pack, vectorized (R12 version).
// ---------------------------------------------------------------------------
__global__ void norm_rope_h(const int* __restrict__ pos,
                            const float* __restrict__ qw,
                            const float* __restrict__ kw) {
    int gw = (blockIdx.x * blockDim.x + threadIdx.x) >> 5;
    int lane = threadIdx.x & 31;
    int grp = lane >> 3, li = lane & 7;
    int idx = gw * 4 + grp;
    if (idx >= TOKENS * NH_ALL) return;
    int token = idx / NH_ALL;
    int h = idx - token * NH_ALL;

    const float* ptr = g_qkv + (size_t)token * QKV_DIM + h * DHEAD;
    __half* outp = g_qkvh + (size_t)token * QKV_DIM + h * DHEAD;
    float4 x1 = *(const float4*)(ptr + li * 4);
    float4 x2 = *(const float4*)(ptr + 32 + li * 4);

    if (h >= HQ + HKV) {   // v: plain convert
        uint2 p1, p2;
        p1.x = packh2(x1.x, x1.y); p1.y = packh2(x1.z, x1.w);
        p2.x = packh2(x2.x, x2.y); p2.y = packh2(x2.z, x2.w);
        *(uint2*)(outp + li * 4) = p1;
        *(uint2*)(outp + 32 + li * 4) = p2;
        return;
    }

    int p = pos[token & (N_SEQ - 1)];
    float ss = x1.x * x1.x + x1.y * x1.y + x1.z * x1.z + x1.w * x1.w
             + x2.x * x2.x + x2.y * x2.y + x2.z * x2.z + x2.w * x2.w;
    ss += __shfl_xor_sync(0xffffffffu, ss, 1);
    ss += __shfl_xor_sync(0xffffffffu, ss, 2);
    ss += __shfl_xor_sync(0xffffffffu, ss, 4);
    float r = rsqrtf(ss * (1.0f / 64.0f) + 1e-6f);

    const float* wv = (h < HQ) ? qw : kw;
    float4 w1 = *(const float4*)(wv + li * 4);
    float4 w2 = *(const float4*)(wv + 32 + li * 4);
    float sc = (h < HQ) ? 0.125f : 1.0f;

    float a1[4] = {x1.x * r * w1.x, x1.y * r * w1.y, x1.z * r * w1.z, x1.w * r * w1.w};
    float a2[4] = {x2.x * r * w2.x, x2.y * r * w2.y, x2.z * r * w2.z, x2.w * r * w2.w};

    float y1[4], y2[4];
#pragma unroll
    for (int j = 0; j < 4; j++) {
        int d = li * 4 + j;
        float inv = expf(-(float)(2 * d) * (9.210340371976184f / 64.0f));
        float sv, cv;
        sincosf((float)p * inv, &sv, &cv);
        y1[j] = (a1[j] * cv - a2[j] * sv) * sc;
        y2[j] = (a1[j] * sv + a2[j] * cv) * sc;
    }
    uint2 p1, p2;
    p1.x = packh2(y1[0], y1[1]); p1.y = packh2(y1[2], y1[3]);
    p2.x = packh2(y2[0], y2[1]); p2.y = packh2(y2[2], y2[3]);
    *(uint2*)(outp + li * 4) = p1;
    *(uint2*)(outp + 32 + li * 4) = p2;
}

// ---------------------------------------------------------------------------
// FP16 tensor-core causal GQA flash attention (unchanged from R11/R12 best).
// ---------------------------------------------------------------------------
#define ATTN_SMEM_WORDS (4096 + 2048 + 2048 + 4096)
#define ATTN_SMEM_BYTES (ATTN_SMEM_WORDS * 4)

__global__ __launch_bounds__(256) void attn_mma() {
    extern __shared__ uint32_t smu[];
    uint32_t* Qfr = smu;             // 4096
    uint32_t* Kfr = smu + 4096;      // 2048
    uint32_t* Vfr = smu + 6144;      // 2048
    uint32_t* Pfr = smu + 8192;      // 4096: per-warp 512

    int qb = (gridDim.x - 1) - blockIdx.x;
    int h = blockIdx.y, b = blockIdx.z;
    int hk4 = h >> 2;
    int tid = threadIdx.x, lane = tid & 31, w = tid >> 5;
    int g = lane >> 2, t = lane & 3;
    size_t base = (size_t)b * N_SEQ;
    int q0 = qb * 128;

#pragma unroll
    for (int s = 0; s < 4; s++) {
        int idx = tid + s * 256;
        int row = idx >> 3, c = idx & 7;
        uint4 qv = *(const uint4*)&g_qkvh[(base + q0 + row) * QKV_DIM + h * DHEAD + c * 8];
        int wq = row >> 4, ishi = (row >> 3) & 1, gq = row & 7;
        int hh = c & 1, ik = c >> 1;
        const uint32_t* pq = (const uint32_t*)&qv;
#pragma unroll
        for (int j = 0; j < 4; j++) {
            int slot = (gq * 4 + j) ^ ((ik & 3) * 4);
            Qfr[((wq * 4 + ik) * 32 + slot) * 4 + ishi + 2 * hh] = pq[j];
        }
    }

    uint4 rk[2], rv[2];
    const int nb = 2 * qb + 2;

#define LOADKV(kb_)                                                            \
    {                                                                          \
        int k0_ = (kb_) * 64;                                                  \
        _Pragma("unroll")                                                      \
        for (int s = 0; s < 2; s++) {                                          \
            int idx = tid + s * 256;                                           \
            int key = idx >> 3, c = idx & 7;                                   \
            size_t toff = (base + k0_ + key) * QKV_DIM;                        \
            rk[s] = *(const uint4*)&g_qkvh[toff + (HQ + hk4) * DHEAD + c * 8]; \
            rv[s] = *(const uint4*)&g_qkvh[toff + (HQ + HKV + hk4) * DHEAD + c * 8]; \
        }                                                                      \
    }

#define STAGEKV()                                                              \
    {                                                                          \
        __half* vh = (__half*)Vfr;                                             \
        _Pragma("unroll")                                                      \
        for (int s = 0; s < 2; s++) {                                          \
            int idx = tid + s * 256;                                           \
            int key = idx >> 3, c = idx & 7;                                   \
            int in = key >> 3, gb = key & 7;                                   \
            int hh = c & 1, ik = c >> 1;                                       \
            const uint32_t* pk = (const uint32_t*)&rk[s];                      \
            _Pragma("unroll")                                                  \
            for (int j = 0; j < 4; j++) {                                      \
                int slK = (gb * 4 + j) ^ ((ik & 3) * 4);                       \
                Kfr[((in * 4 + ik) * 32 + slK) * 2 + hh] = pk[j];              \
            }                                                                  \
            int tv = (key >> 1) & 3, hv = (key >> 3) & 1, ikv = key >> 4;      \
            int keylo = key & 1;                                               \
            const __half* ph = (const __half*)&rv[s];                          \
            _Pragma("unroll")                                                  \
            for (int e = 0; e < 8; e++) {                                      \
                int d = c * 8 + e;                                             \
                int dt = d >> 3, gv = d & 7;                                   \
                int slV = (gv * 4 + tv) ^ ((dt & 3) * 4);                      \
                int hidx = ((((ikv * 8 + dt) * 32 + slV) * 2 + hv) << 1) | keylo; \
                vh[hidx] = ph[e];                                              \
            }                                                                  \
        }                                                                      \
    }

    float m0 = -CUDART_INF_F, m1 = -CUDART_INF_F, l0 = 0.f, l1 = 0.f;
    float o[8][4];
#pragma unroll
    for (int dt = 0; dt < 8; dt++)
#pragma unroll
        for (int j = 0; j < 4; j++) o[dt][j] = 0.f;

    uint32_t* Pw = Pfr + w * 512;
    const int row0 = q0 + w * 16 + g;

    LOADKV(0);

    for (int kb = 0; kb < nb; kb++) {
        if (kb > 0) __syncthreads();
        STAGEKV();
        __syncthreads();
        if (kb + 1 < nb) LOADKV(kb + 1);

        float sacc[8][4];
#pragma unroll
        for (int n = 0; n < 8; n++)
#pragma unroll
            for (int j = 0; j < 4; j++) sacc[n][j] = 0.f;

#pragma unroll
        for (int ik = 0; ik < 4; ik++) {
            uint4 aq = *(const uint4*)&Qfr[((w * 4 + ik) * 32 + (lane ^ ((ik & 3) * 4))) * 4];
            const uint32_t a4[4] = {aq.x, aq.y, aq.z, aq.w};
#pragma unroll
            for (int n = 0; n < 8; n++) {
                uint2 bk = *(const uint2*)&Kfr[((n * 4 + ik) * 32 + (lane ^ ((ik & 3) * 4))) * 2];
                const uint32_t b2[2] = {bk.x, bk.y};
                mma_f16(sacc[n], a4, b2);
            }
        }

        if (kb >= 2 * qb) {
            int k0 = kb * 64;
#pragma unroll
            for (int n = 0; n < 8; n++) {
                int cb = k0 + n * 8 + 2 * t;
                if (cb > row0)     sacc[n][0] = -1e30f;
                if (cb + 1 > row0) sacc[n][1] = -1e30f;
                if (cb > row0 + 8)     sacc[n][2] = -1e30f;
                if (cb + 1 > row0 + 8) sacc[n][3] = -1e30f;
            }
        }

        float mx0 = -1e30f, mx1 = -1e30f;
#pragma unroll
        for (int n = 0; n < 8; n++) {
            mx0 = fmaxf(mx0, fmaxf(sacc[n][0], sacc[n][1]));
            mx1 = fmaxf(mx1, fmaxf(sacc[n][2], sacc[n][3]));
        }
        mx0 = fmaxf(mx0, __shfl_xor_sync(0xffffffffu, mx0, 1));
        mx0 = fmaxf(mx0, __shfl_xor_sync(0xffffffffu, mx0, 2));
        mx1 = fmaxf(mx1, __shfl_xor_sync(0xffffffffu, mx1, 1));
        mx1 = fmaxf(mx1, __shfl_xor_sync(0xffffffffu, mx1, 2));

        float mn0 = fmaxf(m0, mx0), mn1 = fmaxf(m1, mx1);
        float c0 = __expf(m0 - mn0), c1 = __expf(m1 - mn1);
        float s0 = 0.f, s1 = 0.f;
#pragma unroll
        for (int n = 0; n < 8; n++) {
            sacc[n][0] = __expf(sacc[n][0] - mn0);
            sacc[n][1] = __expf(sacc[n][1] - mn0);
            sacc[n][2] = __expf(sacc[n][2] - mn1);
            sacc[n][3] = __expf(sacc[n][3] - mn1);
            s0 += sacc[n][0] + sacc[n][1];
            s1 += sacc[n][2] + sacc[n][3];
        }
        s0 += __shfl_xor_sync(0xffffffffu, s0, 1);
        s0 += __shfl_xor_sync(0xffffffffu, s0, 2);
        s1 += __shfl_xor_sync(0xffffffffu, s1, 1);
        s1 += __shfl_xor_sync(0xffffffffu, s1, 2);
        l0 = l0 * c0 + s0; l1 = l1 * c1 + s1;
        m0 = mn0; m1 = mn1;
#pragma unroll
        for (int dt = 0; dt < 8; dt++) {
            o[dt][0] *= c0; o[dt][1] *= c0;
            o[dt][2] *= c1; o[dt][3] *= c1;
        }

#pragma unroll
        for (int n = 0; n < 8; n++) {
            int ikp = n >> 1, hkp = n & 1;
            Pw[(ikp * 32 + g * 4 + t) * 4 + 0 + 2 * hkp] = packh2(sacc[n][0], sacc[n][1]);
            Pw[(ikp * 32 + g * 4 + t) * 4 + 1 + 2 * hkp] = packh2(sacc[n][2], sacc[n][3]);
        }
        __syncwarp();

#pragma unroll
        for (int ik = 0; ik < 4; ik++) {
            uint4 ap = *(const uint4*)&Pw[(ik * 32 + lane) * 4];
            const uint32_t a4[4] = {ap.x, ap.y, ap.z, ap.w};
#pragma unroll
            for (int dt = 0; dt < 8; dt++) {
                uint2 bv = *(const uint2*)&Vfr[((ik * 8 + dt) * 32 + (lane ^ ((dt & 3) * 4))) * 2];
                const uint32_t b2[2] = {bv.x, bv.y};
                mma_f16(o[dt], a4, b2);
            }
        }
    }

    float i0 = 1.f / l0, i1 = 1.f / l1;
#pragma unroll
    for (int dt = 0; dt < 8; dt++) {
        int col = h * DHEAD + dt * 8 + 2 * t;
        *(uint32_t*)&g_yh[(base + row0) * DMODEL + col] = packh2(o[dt][0] * i0, o[dt][1] * i0);
        *(uint32_t*)&g_yh[(base + row0 + 8) * DMODEL + col] = packh2(o[dt][2] * i1, o[dt][3] * i1);
    }
#undef LOADKV
#undef STAGEKV
}

// ---------------------------------------------------------------------------
// Launch
// ---------------------------------------------------------------------------
extern "C" void kernel_launch(void* const* d_in, const int* in_sizes, int n_in,
                              void* d_out, int out_size) {
    const float* x     = (const float*)d_in[0];
    const int*   pos   = (const int*)d_in[2];
    const float* qkv_w = (const float*)d_in[3];
    const float* out_w = (const float*)d_in[4];
    const float* qnw   = (const float*)d_in[5];
    const float* knw   = (const float*)d_in[6];
    float* out = (float*)d_out;

    float *qkv_buf;
    __half *xh, *wqh, *woh, *yh;
    cudaGetSymbolAddress((void**)&qkv_buf, g_qkv);
    cudaGetSymbolAddress((void**)&xh, g_xh);
    cudaGetSymbolAddress((void**)&wqh, g_wqh);
    cudaGetSymbolAddress((void**)&woh, g_woh);
    cudaGetSymbolAddress((void**)&yh, g_yh);

    cudaFuncSetAttribute(gemm_h16, cudaFuncAttributeMaxDynamicSharedMemorySize,
                         GEMM_SMEM_BYTES);
    cudaFuncSetAttribute(attn_mma, cudaFuncAttributeMaxDynamicSharedMemorySize,
                         ATTN_SMEM_BYTES);

    // 0) one-time fp16 conversions
    {
        int n4;
        n4 = TOKENS * DMODEL / 4;
        f32h<<<(n4 + 255) / 256, 256>>>(x, xh, n4);
        n4 = QKV_DIM * DMODEL / 4;
        f32h<<<(n4 + 255) / 256, 256>>>(qkv_w, wqh, n4);
        n4 = DMODEL * DMODEL / 4;
        f32h<<<(n4 + 255) / 256, 256>>>(out_w, woh, n4);
    }
    // 1) QKV projection (4-stage cp.async pipeline, dynamic smem)
    gemm_h16<<<dim3(QKV_DIM / 128, TOKENS / 128), 256, GEMM_SMEM_BYTES>>>(
        xh, wqh, qkv_buf, TOKENS, QKV_DIM, DMODEL);
    // 2) RMSNorm + RoPE + fp16 pack
    {
        int nidx = TOKENS * NH_ALL;
        int warps = (nidx + 3) / 4;
        int threads = warps * 32;
        norm_rope_h<<<(threads + 255) / 256, 256>>>(pos, qnw, knw);
    }
    // 3) Attention (fp16 in, fp16 out)
    attn_mma<<<dim3(N_SEQ / 128, HQ, B_SZ), 256, ATTN_SMEM_BYTES>>>();
    // 4) Output projection
    gemm_h16<<<dim3(DMODEL / 128, TOKENS / 128), 256, GEMM_SMEM_BYTES>>>(
        yh, woh, out, TOKENS, DMODEL, DMODEL);
}

// round 16
// speedup vs baseline: 1.0135x; 1.0131x over previous
#include <cuda_runtime.h>
#include <cuda_fp16.h>
#include <math_constants.h>
#include <cstdint>

// Problem constants
#define B_SZ    2
#define N_SEQ   2048
#define DMODEL  2048
#define HQ      32
#define HKV     8
#define DHEAD   64
#define QKV_DIM 3072
#define TOKENS  4096
#define NH_ALL  48            // q(32) + k(8) + v(8)

// Scratch (allocation-free device globals)
__device__ float  g_qkv[(size_t)TOKENS * QKV_DIM];    // fp32 QKV (gemm out)
__device__ __half g_qkvh[(size_t)TOKENS * QKV_DIM];   // fp16 normed/roped
__device__ __half g_xh[(size_t)TOKENS * DMODEL];      // fp16 x
__device__ __half g_wqh[(size_t)QKV_DIM * DMODEL];    // fp16 qkv_w
__device__ __half g_woh[(size_t)DMODEL * DMODEL];     // fp16 out_w
__device__ __half g_yh[(size_t)TOKENS * DMODEL];      // fp16 attn out

__device__ __forceinline__ uint32_t packh2(float a, float b) {
    __half2 h = __floats2half2_rn(a, b);
    return *(uint32_t*)&h;
}

__device__ __forceinline__ void mma_f16(float c[4], const uint32_t a[4],
                                        const uint32_t b[2]) {
    asm volatile(
        "mma.sync.aligned.m16n8k16.row.col.f32.f16.f16.f32 "
        "{%0,%1,%2,%3}, {%4,%5,%6,%7}, {%8,%9}, {%0,%1,%2,%3};\n"
        : "+f"(c[0]), "+f"(c[1]), "+f"(c[2]), "+f"(c[3])
        : "r"(a[0]), "r"(a[1]), "r"(a[2]), "r"(a[3]), "r"(b[0]), "r"(b[1]));
}

// ---------------------------------------------------------------------------
// fp32 -> fp16 grid-stride converter (n % 4 == 0)
// ---------------------------------------------------------------------------
__global__ void f32h(const float* __restrict__ in, __half* __restrict__ out,
                     int n4) {
    int i = blockIdx.x * blockDim.x + threadIdx.x;
    if (i >= n4) return;
    float4 v = *(const float4*)(in + (size_t)i * 4);
    uint2 p;
    p.x = packh2(v.x, v.y);
    p.y = packh2(v.z, v.w);
    *(uint2*)(out + (size_t)i * 4) = p;
}

// ---------------------------------------------------------------------------
// FP16-in GEMM (R12 best-measured config): C[M,N](fp32) = A[M,K] * B[N,K]^T.
// 128x128 CTA tile, BK=32, 8 warps (2x4), warp tile 64x32.
// Double-buffered static smem; one barrier per K-step. 2 CTAs/SM.
// ---------------------------------------------------------------------------
__global__ __launch_bounds__(256, 2) void gemm_h16(const __half* __restrict__ A,
                                                   const __half* __restrict__ Bm,
                                                   float* __restrict__ C,
                                                   int M, int N, int K) {
    __shared__ uint32_t Afr[2][2048];   // 8 m16 x 2 ik x 32 lanes x 4 regs
    __shared__ uint32_t Bfr[2][2048];   // 16 n8 x 2 ik x 32 lanes x 2 regs

    const int tid = threadIdx.x;
    const int lane = tid & 31, warp = tid >> 5;
    const int wm = warp >> 2, wn = warp & 3;   // 2 x 4
    const size_t bm = (size_t)blockIdx.y * 128, bn = (size_t)blockIdx.x * 128;

    const __half* Abase = A + bm * K;
    const __half* Bbase = Bm + bn * K;

    uint4 ra[2], rb[2];
    float acc[4][4][4];
#pragma unroll
    for (int im = 0; im < 4; im++)
#pragma unroll
        for (int in = 0; in < 4; in++)
#pragma unroll
            for (int j = 0; j < 4; j++) acc[im][in][j] = 0.f;

#define LOADG(k0)                                                              \
    {                                                                          \
        _Pragma("unroll")                                                      \
        for (int s = 0; s < 2; s++) {                                          \
            int idx = tid + s * 256;                                           \
            int row = idx >> 2, c = idx & 3;                                   \
            ra[s] = *(const uint4*)(Abase + (size_t)row * K + (k0) + c * 8);   \
            rb[s] = *(const uint4*)(Bbase + (size_t)row * K + (k0) + c * 8);   \
        }                                                                      \
    }

#define STAGE(b_)                                                              \
    {                                                                          \
        _Pragma("unroll")                                                      \
        for (int s = 0; s < 2; s++) {                                          \
            int idx = tid + s * 256;                                           \
            int row = idx >> 2, c = idx & 3;                                   \
            int g = row & 7, ishi = (row >> 3) & 1, im = row >> 4;             \
            int inb = row >> 3;                                                \
            int hk = c & 1, ik = c >> 1;                                       \
            const uint32_t* pa = (const uint32_t*)&ra[s];                      \
            const uint32_t* pb = (const uint32_t*)&rb[s];                      \
            _Pragma("unroll")                                                  \
            for (int j = 0; j < 4; j++) {                                      \
                Afr[b_][((im * 2 + ik) * 32 + g * 4 + j) * 4 + ishi + 2 * hk] = pa[j]; \
                Bfr[b_][((inb * 2 + ik) * 32 + g * 4 + j) * 2 + hk] = pb[j];   \
            }                                                                  \
        }                                                                      \
    }

    LOADG(0);
    STAGE(0);
    __syncthreads();

    int cur = 0;
    for (int k0 = 32; k0 <= K; k0 += 32) {
        const bool more = (k0 < K);
        if (more) LOADG(k0);

#pragma unroll
        for (int ik = 0; ik < 2; ik++) {
            uint4 af[4];
            uint32_t bf[4][2];
#pragma unroll
            for (int im = 0; im < 4; im++)
                af[im] = *(const uint4*)&Afr[cur][(((wm * 4 + im) * 2 + ik) * 32 + lane) * 4];
#pragma unroll
            for (int in = 0; in < 4; in++) {
                uint2 tt = *(const uint2*)&Bfr[cur][(((wn * 4 + in) * 2 + ik) * 32 + lane) * 2];
                bf[in][0] = tt.x; bf[in][1] = tt.y;
            }
#pragma unroll
            for (int im = 0; im < 4; im++) {
                const uint32_t a4[4] = {af[im].x, af[im].y, af[im].z, af[im].w};
#pragma unroll
                for (int in = 0; in < 4; in++)
                    mma_f16(acc[im][in], a4, bf[in]);
            }
        }

        if (more) STAGE(cur ^ 1);
        __syncthreads();
        cur ^= 1;
    }

#pragma unroll
    for (int im = 0; im < 4; im++) {
#pragma unroll
        for (int in = 0; in < 4; in++) {
            size_t r0 = bm + wm * 64 + im * 16 + (lane >> 2);
            size_t c0 = bn + wn * 32 + in * 8 + (lane & 3) * 2;
            *(float2*)&C[r0 * N + c0] = make_float2(acc[im][in][0], acc[im][in][1]);
            *(float2*)&C[(r0 + 8) * N + c0] = make_float2(acc[im][in][2], acc[im][in][3]);
        }
    }
#undef LOADG
#undef STAGE
}

// ---------------------------------------------------------------------------
// Fused per-head RMSNorm + RoPE + fp16 pack, vectorized (R12 version).
// ---------------------------------------------------------------------------
__global__ void norm_rope_h(const int* __restrict__ pos,
                            const float* __restrict__ qw,
                            const float* __restrict__ kw) {
    int gw = (blockIdx.x * blockDim.x + threadIdx.x) >> 5;
    int lane = threadIdx.x & 31;
    int grp = lane >> 3, li = lane & 7;
    int idx = gw * 4 + grp;
    if (idx >= TOKENS * NH_ALL) return;
    int token = idx / NH_ALL;
    int h = idx - token * NH_ALL;

    const float* ptr = g_qkv + (size_t)token * QKV_DIM + h * DHEAD;
    __half* outp = g_qkvh + (size_t)token * QKV_DIM + h * DHEAD;
    float4 x1 = *(const float4*)(ptr + li * 4);
    float4 x2 = *(const float4*)(ptr + 32 + li * 4);

    if (h >= HQ + HKV) {   // v: plain convert
        uint2 p1, p2;
        p1.x = packh2(x1.x, x1.y); p1.y = packh2(x1.z, x1.w);
        p2.x = packh2(x2.x, x2.y); p2.y = packh2(x2.z, x2.w);
        *(uint2*)(outp + li * 4) = p1;
        *(uint2*)(outp + 32 + li * 4) = p2;
        return;
    }

    int p = pos[token & (N_SEQ - 1)];
    float ss = x1.x * x1.x + x1.y * x1.y + x1.z * x1.z + x1.w * x1.w
             + x2.x * x2.x + x2.y * x2.y + x2.z * x2.z + x2.w * x2.w;
    ss += __shfl_xor_sync(0xffffffffu, ss, 1);
    ss += __shfl_xor_sync(0xffffffffu, ss, 2);
    ss += __shfl_xor_sync(0xffffffffu, ss, 4);
    float r = rsqrtf(ss * (1.0f / 64.0f) + 1e-6f);

    const float* wv = (h < HQ) ? qw : kw;
    float4 w1 = *(const float4*)(wv + li * 4);
    float4 w2 = *(const float4*)(wv + 32 + li * 4);
    float sc = (h < HQ) ? 0.125f : 1.0f;

    float a1[4] = {x1.x * r * w1.x, x1.y * r * w1.y, x1.z * r * w1.z, x1.w * r * w1.w};
    float a2[4] = {x2.x * r * w2.x, x2.y * r * w2.y, x2.z * r * w2.z, x2.w * r * w2.w};

    float y1[4], y2[4];
#pragma unroll
    for (int j = 0; j < 4; j++) {
        int d = li * 4 + j;
        float inv = expf(-(float)(2 * d) * (9.210340371976184f / 64.0f));
        float sv, cv;
        sincosf((float)p * inv, &sv, &cv);
        y1[j] = (a1[j] * cv - a2[j] * sv) * sc;
        y2[j] = (a1[j] * sv + a2[j] * cv) * sc;
    }
    uint2 p1, p2;
    p1.x = packh2(y1[0], y1[1]); p1.y = packh2(y1[2], y1[3]);
    p2.x = packh2(y2[0], y2[1]); p2.y = packh2(y2[2], y2[3]);
    *(uint2*)(outp + li * 4) = p1;
    *(uint2*)(outp + 32 + li * 4) = p2;
}

// ---------------------------------------------------------------------------
// FP16 tensor-core causal GQA flash attention.
// __launch_bounds__(256, 2): force <=128 regs -> 2 CTAs/SM (16 warps).
// ---------------------------------------------------------------------------
#define ATTN_SMEM_WORDS (4096 + 2048 + 2048 + 4096)
#define ATTN_SMEM_BYTES (ATTN_SMEM_WORDS * 4)

__global__ __launch_bounds__(256, 2) void attn_mma() {
    extern __shared__ uint32_t smu[];
    uint32_t* Qfr = smu;             // 4096
    uint32_t* Kfr = smu + 4096;      // 2048
    uint32_t* Vfr = smu + 6144;      // 2048
    uint32_t* Pfr = smu + 8192;      // 4096: per-warp 512

    int qb = (gridDim.x - 1) - blockIdx.x;
    int h = blockIdx.y, b = blockIdx.z;
    int hk4 = h >> 2;
    int tid = threadIdx.x, lane = tid & 31, w = tid >> 5;
    int g = lane >> 2, t = lane & 3;
    size_t base = (size_t)b * N_SEQ;
    int q0 = qb * 128;

#pragma unroll
    for (int s = 0; s < 4; s++) {
        int idx = tid + s * 256;
        int row = idx >> 3, c = idx & 7;
        uint4 qv = *(const uint4*)&g_qkvh[(base + q0 + row) * QKV_DIM + h * DHEAD + c * 8];
        int wq = row >> 4, ishi = (row >> 3) & 1, gq = row & 7;
        int hh = c & 1, ik = c >> 1;
        const uint32_t* pq = (const uint32_t*)&qv;
#pragma unroll
        for (int j = 0; j < 4; j++) {
            int slot = (gq * 4 + j) ^ ((ik & 3) * 4);
            Qfr[((wq * 4 + ik) * 32 + slot) * 4 + ishi + 2 * hh] = pq[j];
        }
    }

    uint4 rk[2], rv[2];
    const int nb = 2 * qb + 2;

#define LOADKV(kb_)                                                            \
    {                                                                          \
        int k0_ = (kb_) * 64;                                                  \
        _Pragma("unroll")                                                      \
        for (int s = 0; s < 2; s++) {                                          \
            int idx = tid + s * 256;                                           \
            int key = idx >> 3, c = idx & 7;                                   \
            size_t toff = (base + k0_ + key) * QKV_DIM;                        \
            rk[s] = *(const uint4*)&g_qkvh[toff + (HQ + hk4) * DHEAD + c * 8]; \
            rv[s] = *(const uint4*)&g_qkvh[toff + (HQ + HKV + hk4) * DHEAD + c * 8]; \
        }                                                                      \
    }

#define STAGEKV()                                                              \
    {                                                                          \
        __half* vh = (__half*)Vfr;                                             \
        _Pragma("unroll")                                                      \
        for (int s = 0; s < 2; s++) {                                          \
            int idx = tid + s * 256;                                           \
            int key = idx >> 3, c = idx & 7;                                   \
            int in = key >> 3, gb = key & 7;                                   \
            int hh = c & 1, ik = c >> 1;                                       \
            const uint32_t* pk = (const uint32_t*)&rk[s];                      \
            _Pragma("unroll")                                                  \
            for (int j = 0; j < 4; j++) {                                      \
                int slK = (gb * 4 + j) ^ ((ik & 3) * 4);                       \
                Kfr[((in * 4 + ik) * 32 + slK) * 2 + hh] = pk[j];              \
            }                                                                  \
            int tv = (key >> 1) & 3, hv = (key >> 3) & 1, ikv = key >> 4;      \
            int keylo = key & 1;                                               \
            const __half* ph = (const __half*)&rv[s];                          \
            _Pragma("unroll")                                                  \
            for (int e = 0; e < 8; e++) {                                      \
                int d = c * 8 + e;                                             \
                int dt = d >> 3, gv = d & 7;                                   \
                int slV = (gv * 4 + tv) ^ ((dt & 3) * 4);                      \
                int hidx = ((((ikv * 8 + dt) * 32 + slV) * 2 + hv) << 1) | keylo; \
                vh[hidx] = ph[e];                                              \
            }                                                                  \
        }                                                                      \
    }

    float m0 = -CUDART_INF_F, m1 = -CUDART_INF_F, l0 = 0.f, l1 = 0.f;
    float o[8][4];
#pragma unroll
    for (int dt = 0; dt < 8; dt++)
#pragma unroll
        for (int j = 0; j < 4; j++) o[dt][j] = 0.f;

    uint32_t* Pw = Pfr + w * 512;
    const int row0 = q0 + w * 16 + g;

    LOADKV(0);

    for (int kb = 0; kb < nb; kb++) {
        if (kb > 0) __syncthreads();
        STAGEKV();
        __syncthreads();
        if (kb + 1 < nb) LOADKV(kb + 1);

        float sacc[8][4];
#pragma unroll
        for (int n = 0; n < 8; n++)
#pragma unroll
            for (int j = 0; j < 4; j++) sacc[n][j] = 0.f;

#pragma unroll
        for (int ik = 0; ik < 4; ik++) {
            uint4 aq = *(const uint4*)&Qfr[((w * 4 + ik) * 32 + (lane ^ ((ik & 3) * 4))) * 4];
            const uint32_t a4[4] = {aq.x, aq.y, aq.z, aq.w};
#pragma unroll
            for (int n = 0; n < 8; n++) {
                uint2 bk = *(const uint2*)&Kfr[((n * 4 + ik) * 32 + (lane ^ ((ik & 3) * 4))) * 2];
                const uint32_t b2[2] = {bk.x, bk.y};
                mma_f16(sacc[n], a4, b2);
            }
        }

        if (kb >= 2 * qb) {
            int k0 = kb * 64;
#pragma unroll
            for (int n = 0; n < 8; n++) {
                int cb = k0 + n * 8 + 2 * t;
                if (cb > row0)     sacc[n][0] = -1e30f;
                if (cb + 1 > row0) sacc[n][1] = -1e30f;
                if (cb > row0 + 8)     sacc[n][2] = -1e30f;
                if (cb + 1 > row0 + 8) sacc[n][3] = -1e30f;
            }
        }

        float mx0 = -1e30f, mx1 = -1e30f;
#pragma unroll
        for (int n = 0; n < 8; n++) {
            mx0 = fmaxf(mx0, fmaxf(sacc[n][0], sacc[n][1]));
            mx1 = fmaxf(mx1, fmaxf(sacc[n][2], sacc[n][3]));
        }
        mx0 = fmaxf(mx0, __shfl_xor_sync(0xffffffffu, mx0, 1));
        mx0 = fmaxf(mx0, __shfl_xor_sync(0xffffffffu, mx0, 2));
        mx1 = fmaxf(mx1, __shfl_xor_sync(0xffffffffu, mx1, 1));
        mx1 = fmaxf(mx1, __shfl_xor_sync(0xffffffffu, mx1, 2));

        float mn0 = fmaxf(m0, mx0), mn1 = fmaxf(m1, mx1);
        float c0 = __expf(m0 - mn0), c1 = __expf(m1 - mn1);
        float s0 = 0.f, s1 = 0.f;
#pragma unroll
        for (int n = 0; n < 8; n++) {
            sacc[n][0] = __expf(sacc[n][0] - mn0);
            sacc[n][1] = __expf(sacc[n][1] - mn0);
            sacc[n][2] = __expf(sacc[n][2] - mn1);
            sacc[n][3] = __expf(sacc[n][3] - mn1);
            s0 += sacc[n][0] + sacc[n][1];
            s1 += sacc[n][2] + sacc[n][3];
        }
        s0 += __shfl_xor_sync(0xffffffffu, s0, 1);
        s0 += __shfl_xor_sync(0xffffffffu, s0, 2);
        s1 += __shfl_xor_sync(0xffffffffu, s1, 1);
        s1 += __shfl_xor_sync(0xffffffffu, s1, 2);
        l0 = l0 * c0 + s0; l1 = l1 * c1 + s1;
        m0 = mn0; m1 = mn1;
#pragma unroll
        for (int dt = 0; dt < 8; dt++) {
            o[dt][0] *= c0; o[dt][1] *= c0;
            o[dt][2] *= c1; o[dt][3] *= c1;
        }

#pragma unroll
        for (int n = 0; n < 8; n++) {
            int ikp = n >> 1, hkp = n & 1;
            Pw[(ikp * 32 + g * 4 + t) * 4 + 0 + 2 * hkp] = packh2(sacc[n][0], sacc[n][1]);
            Pw[(ikp * 32 + g * 4 + t) * 4 + 1 + 2 * hkp] = packh2(sacc[n][2], sacc[n][3]);
        }
        __syncwarp();

#pragma unroll
        for (int ik = 0; ik < 4; ik++) {
            uint4 ap = *(const uint4*)&Pw[(ik * 32 + lane) * 4];
            const uint32_t a4[4] = {ap.x, ap.y, ap.z, ap.w};
#pragma unroll
            for (int dt = 0; dt < 8; dt++) {
                uint2 bv = *(const uint2*)&Vfr[((ik * 8 + dt) * 32 + (lane ^ ((dt & 3) * 4))) * 2];
                const uint32_t b2[2] = {bv.x, bv.y};
                mma_f16(o[dt], a4, b2);
            }
        }
    }

    float i0 = 1.f / l0, i1 = 1.f / l1;
#pragma unroll
    for (int dt = 0; dt < 8; dt++) {
        int col = h * DHEAD + dt * 8 + 2 * t;
        *(uint32_t*)&g_yh[(base + row0) * DMODEL + col] = packh2(o[dt][0] * i0, o[dt][1] * i0);
        *(uint32_t*)&g_yh[(base + row0 + 8) * DMODEL + col] = packh2(o[dt][2] * i1, o[dt][3] * i1);
    }
#undef LOADKV
#undef STAGEKV
}

// ---------------------------------------------------------------------------
// Launch
// ---------------------------------------------------------------------------
extern "C" void kernel_launch(void* const* d_in, const int* in_sizes, int n_in,
                              void* d_out, int out_size) {
    const float* x     = (const float*)d_in[0];
    const int*   pos   = (const int*)d_in[2];
    const float* qkv_w = (const float*)d_in[3];
    const float* out_w = (const float*)d_in[4];
    const float* qnw   = (const float*)d_in[5];
    const float* knw   = (const float*)d_in[6];
    float* out = (float*)d_out;

    float *qkv_buf;
    __half *xh, *wqh, *woh, *yh;
    cudaGetSymbolAddress((void**)&qkv_buf, g_qkv);
    cudaGetSymbolAddress((void**)&xh, g_xh);
    cudaGetSymbolAddress((void**)&wqh, g_wqh);
    cudaGetSymbolAddress((void**)&woh, g_woh);
    cudaGetSymbolAddress((void**)&yh, g_yh);

    cudaFuncSetAttribute(attn_mma, cudaFuncAttributeMaxDynamicSharedMemorySize,
                         ATTN_SMEM_BYTES);

    // 0) one-time fp16 conversions
    {
        int n4;
        n4 = TOKENS * DMODEL / 4;
        f32h<<<(n4 + 255) / 256, 256>>>(x, xh, n4);
        n4 = QKV_DIM * DMODEL / 4;
        f32h<<<(n4 + 255) / 256, 256>>>(qkv_w, wqh, n4);
        n4 = DMODEL * DMODEL / 4;
        f32h<<<(n4 + 255) / 256, 256>>>(out_w, woh, n4);
    }
    // 1) QKV projection (R12 best gemm)
    gemm_h16<<<dim3(QKV_DIM / 128, TOKENS / 128), 256>>>(xh, wqh, qkv_buf,
                                                         TOKENS, QKV_DIM, DMODEL);
    // 2) RMSNorm + RoPE + fp16 pack
    {
        int nidx = TOKENS * NH_ALL;
        int warps = (nidx + 3) / 4;
        int threads = warps * 32;
        norm_rope_h<<<(threads + 255) / 256, 256>>>(pos, qnw, knw);
    }
    // 3) Attention (fp16 in/out, 2 CTAs/SM)
    attn_mma<<<dim3(N_SEQ / 128, HQ, B_SZ), 256, ATTN_SMEM_BYTES>>>();
    // 4) Output projection
    gemm_h16<<<dim3(DMODEL / 128, TOKENS / 128), 256>>>(yh, woh, out,
                                                        TOKENS, DMODEL, DMODEL);
}